// round 4
// baseline (speedup 1.0000x reference)
#include <cuda_runtime.h>
#include <cstdint>

// out[t, h] = W[h, seq[t]] + b[h]
// seq: int32 [n_tok], W: fp32 [H, V] row-major, b: fp32 [H], out: fp32 [n_tok, H]
//
// Pipeline (4 launches):
//  1) hist    : bucket counts of v>>3 (one 32B W sector per bucket)
//  2) scan    : exclusive scan of counts -> g_off; ALSO re-zeroes g_hist so
//               the next invocation starts clean (g_hist is zero-initialized
//               at module load; every call leaves it zeroed -> deterministic)
//  3) scatter : counting-sort (v, t) pairs by bucket
//  4) gather  : lanes-along-sorted-v load (few sectors/warp), padded-SMEM
//               transpose, coalesced streaming stores
//
// W is swept nearly sequentially -> each W sector leaves HBM once (~201MB)
// plus the mandatory 128MB output write. DRAM floor ~47us @ 7TB/s.

#define H_DIM 1024
#define TOK_PER_BLK 32
#define THREADS 256
#define HCHUNK 256
#define NCHUNK (H_DIM / HCHUNK)   // 4

#define MAX_N 65536
#define MAX_BUCKETS 8192
#define SCAN_THREADS 1024
#define SCAN_PER 8                 // 1024*8 = 8192 >= MAX_BUCKETS

__device__ int g_hist[MAX_BUCKETS];   // zero at load; scan re-zeroes after use
__device__ int g_off[MAX_BUCKETS];
__device__ int g_sorted_v[MAX_N];
__device__ int g_sorted_t[MAX_N];

// ---------------- sort pipeline ----------------

__global__ __launch_bounds__(512)
void hist_kernel(const int4* __restrict__ seq4, int n4) {
    int i = blockIdx.x * blockDim.x + threadIdx.x;
    if (i < n4) {
        int4 v = seq4[i];
        atomicAdd(&g_hist[v.x >> 3], 1);
        atomicAdd(&g_hist[v.y >> 3], 1);
        atomicAdd(&g_hist[v.z >> 3], 1);
        atomicAdd(&g_hist[v.w >> 3], 1);
    }
}

__global__ __launch_bounds__(SCAN_THREADS)
void scan_kernel(int nbuckets) {
    __shared__ int warp_sums[32];
    const int tid  = threadIdx.x;
    const int lane = tid & 31;
    const int w    = tid >> 5;

    int vals[SCAN_PER];
    int local = 0;
    #pragma unroll
    for (int i = 0; i < SCAN_PER; i++) {
        int idx = tid * SCAN_PER + i;
        vals[i] = (idx < nbuckets) ? g_hist[idx] : 0;
        local += vals[i];
    }

    int x = local;
    #pragma unroll
    for (int d = 1; d < 32; d <<= 1) {
        int y = __shfl_up_sync(0xFFFFFFFFu, x, d);
        if (lane >= d) x += y;
    }
    if (lane == 31) warp_sums[w] = x;
    __syncthreads();

    if (w == 0) {
        int s = warp_sums[lane];
        #pragma unroll
        for (int d = 1; d < 32; d <<= 1) {
            int y = __shfl_up_sync(0xFFFFFFFFu, s, d);
            if (lane >= d) s += y;
        }
        warp_sums[lane] = s;
    }
    __syncthreads();

    int thread_excl = (w > 0 ? warp_sums[w - 1] : 0) + (x - local);

    int run = thread_excl;
    #pragma unroll
    for (int i = 0; i < SCAN_PER; i++) {
        int idx = tid * SCAN_PER + i;
        if (idx < nbuckets) {
            g_off[idx]  = run;
            g_hist[idx] = 0;         // leave zeroed for the next invocation
        }
        run += vals[i];
    }
}

__global__ __launch_bounds__(512)
void scatter_kernel(const int4* __restrict__ seq4, int n4) {
    int i = blockIdx.x * blockDim.x + threadIdx.x;
    if (i < n4) {
        int4 v = seq4[i];
        int t = i << 2;
        int p0 = atomicAdd(&g_off[v.x >> 3], 1);
        g_sorted_v[p0] = v.x; g_sorted_t[p0] = t;
        int p1 = atomicAdd(&g_off[v.y >> 3], 1);
        g_sorted_v[p1] = v.y; g_sorted_t[p1] = t + 1;
        int p2 = atomicAdd(&g_off[v.z >> 3], 1);
        g_sorted_v[p2] = v.z; g_sorted_t[p2] = t + 2;
        int p3 = atomicAdd(&g_off[v.w >> 3], 1);
        g_sorted_v[p3] = v.w; g_sorted_t[p3] = t + 3;
    }
}

// ---------------- main gather ----------------

__global__ __launch_bounds__(THREADS)
void onehot_gather_xpose_kernel(const float* __restrict__ W,
                                const float* __restrict__ bias,
                                float* __restrict__ out,
                                int n_tok, int V) {
    __shared__ float s_w[HCHUNK][TOK_PER_BLK + 1];  // pad -> conflict-free both phases
    __shared__ int s_t[TOK_PER_BLK];
    __shared__ int s_v[TOK_PER_BLK];

    const int tid  = threadIdx.x;
    const int lane = tid & 31;
    const int w    = tid >> 5;
    const int base = blockIdx.x * TOK_PER_BLK;

    if (tid < TOK_PER_BLK) {
        int j = base + tid;
        s_v[tid] = (j < n_tok) ? g_sorted_v[j] : 0;   // clamp: valid addr
        s_t[tid] = (j < n_tok) ? g_sorted_t[j] : -1;  // -1 -> skip store
    }
    __syncthreads();

    // Load phase: lane owns token 'lane' (sorted values -> few sectors/warp).
    const int my_v = s_v[lane];

    // Store phase: warp w owns tokens 4w..4w+3.
    int st_t[4];
    #pragma unroll
    for (int q = 0; q < 4; q++) st_t[q] = s_t[(w << 2) + q];

    #pragma unroll
    for (int c = 0; c < NCHUNK; c++) {
        const int h_base = c * HCHUNK;

        // ---- load phase: 32 independent gathers per thread ----
        #pragma unroll
        for (int i = 0; i < HCHUNK / 8; i++) {
            int h_local = (i << 3) + w;  // warp w covers h_local = w, w+8, ...
            float val = __ldg(W + (size_t)(h_base + h_local) * (size_t)V + my_v);
            s_w[h_local][lane] = val;    // stride-1 across lanes: conflict-free
        }

        // bias for this lane's HCHUNK/32 h positions in the chunk
        float bl[HCHUNK / 32];
        #pragma unroll
        for (int hs = 0; hs < HCHUNK / 32; hs++)
            bl[hs] = __ldg(bias + h_base + (hs << 5) + lane);

        __syncthreads();

        // ---- store phase: coalesced 128B rows ----
        #pragma unroll
        for (int q = 0; q < 4; q++) {
            const int j = (w << 2) + q;
            const int t = st_t[q];
            if (t < 0) continue;
            float* dst = out + (size_t)t * H_DIM + h_base;
            #pragma unroll
            for (int hs = 0; hs < HCHUNK / 32; hs++) {
                int h_local = (hs << 5) + lane;
                float r = s_w[h_local][j] + bl[hs];  // stride-(TOK+1): conflict-free
                __stcs(dst + h_local, r);
            }
        }
        __syncthreads();
    }
}

// ---------------- launch ----------------

extern "C" void kernel_launch(void* const* d_in, const int* in_sizes, int n_in,
                              void* d_out, int out_size) {
    const int*   seq  = (const int*)d_in[0];
    const float* W    = (const float*)d_in[1];
    const float* bias = (const float*)d_in[2];
    float*       out  = (float*)d_out;

    const int n_tok = in_sizes[0];            // 32768 (multiple of 4)
    const int H     = in_sizes[2];            // 1024
    const int V     = in_sizes[1] / H;        // 50257
    const int nbuckets = (V + 7) >> 3;        // 6283
    const int n4    = n_tok >> 2;
    (void)out_size; (void)n_in;

    const int4* seq4 = (const int4*)seq;

    hist_kernel<<<(n4 + 511) / 512, 512>>>(seq4, n4);
    scan_kernel<<<1, SCAN_THREADS>>>(nbuckets);
    scatter_kernel<<<(n4 + 511) / 512, 512>>>(seq4, n4);

    const int blocks = (n_tok + TOK_PER_BLK - 1) / TOK_PER_BLK;
    onehot_gather_xpose_kernel<<<blocks, THREADS>>>(W, bias, out, n_tok, V);
}

// round 5
// speedup vs baseline: 1.1004x; 1.1004x over previous
#include <cuda_runtime.h>
#include <cstdint>

// out[t, h] = W[h, seq[t]] + b[h]
// seq: int32 [n_tok], W: fp32 [H, V] row-major, b: fp32 [H], out: fp32 [n_tok, H]
//
// Pipeline (4 launches):
//  1) hist    : bucket counts of v>>3 (one 32B W sector per bucket), scalar
//               1-token/thread (latency-bound; do NOT batch per thread)
//  2) scan    : exclusive scan of counts -> g_off; re-zeroes g_hist so every
//               invocation starts clean (g_hist zero at module load ->
//               deterministic across correctness run + capture + replays)
//  3) scatter : counting-sort (v, t) pairs by bucket, scalar
//  4) gather  : lanes-along-sorted-v load (few sectors/warp), padded-SMEM
//               transpose, coalesced streaming stores. HCHUNK=128 keeps smem
//               at 17KB -> 8 blocks/SM (warp-limited, full occupancy).

#define H_DIM 1024
#define TOK_PER_BLK 32
#define THREADS 256
#define HCHUNK 128
#define NCHUNK (H_DIM / HCHUNK)   // 8

#define MAX_N 65536
#define MAX_BUCKETS 8192
#define SCAN_THREADS 1024
#define SCAN_PER 8                 // 1024*8 = 8192 >= MAX_BUCKETS

__device__ int g_hist[MAX_BUCKETS];   // zero at load; scan re-zeroes after use
__device__ int g_off[MAX_BUCKETS];
__device__ int g_sorted_v[MAX_N];
__device__ int g_sorted_t[MAX_N];

// ---------------- sort pipeline ----------------

__global__ void hist_kernel(const int* __restrict__ seq, int n) {
    int i = blockIdx.x * blockDim.x + threadIdx.x;
    if (i < n) {
        int v = seq[i];
        atomicAdd(&g_hist[v >> 3], 1);
    }
}

__global__ __launch_bounds__(SCAN_THREADS)
void scan_kernel(int nbuckets) {
    __shared__ int warp_sums[32];
    const int tid  = threadIdx.x;
    const int lane = tid & 31;
    const int w    = tid >> 5;

    int vals[SCAN_PER];
    int local = 0;
    #pragma unroll
    for (int i = 0; i < SCAN_PER; i++) {
        int idx = tid * SCAN_PER + i;
        vals[i] = (idx < nbuckets) ? g_hist[idx] : 0;
        local += vals[i];
    }

    int x = local;
    #pragma unroll
    for (int d = 1; d < 32; d <<= 1) {
        int y = __shfl_up_sync(0xFFFFFFFFu, x, d);
        if (lane >= d) x += y;
    }
    if (lane == 31) warp_sums[w] = x;
    __syncthreads();

    if (w == 0) {
        int s = warp_sums[lane];
        #pragma unroll
        for (int d = 1; d < 32; d <<= 1) {
            int y = __shfl_up_sync(0xFFFFFFFFu, s, d);
            if (lane >= d) s += y;
        }
        warp_sums[lane] = s;
    }
    __syncthreads();

    int thread_excl = (w > 0 ? warp_sums[w - 1] : 0) + (x - local);

    int run = thread_excl;
    #pragma unroll
    for (int i = 0; i < SCAN_PER; i++) {
        int idx = tid * SCAN_PER + i;
        if (idx < nbuckets) {
            g_off[idx]  = run;
            g_hist[idx] = 0;         // leave zeroed for next invocation
        }
        run += vals[i];
    }
}

__global__ void scatter_kernel(const int* __restrict__ seq, int n) {
    int t = blockIdx.x * blockDim.x + threadIdx.x;
    if (t < n) {
        int v = seq[t];
        int pos = atomicAdd(&g_off[v >> 3], 1);
        g_sorted_v[pos] = v;
        g_sorted_t[pos] = t;
    }
}

// ---------------- main gather ----------------

__global__ __launch_bounds__(THREADS, 8)
void onehot_gather_xpose_kernel(const float* __restrict__ W,
                                const float* __restrict__ bias,
                                float* __restrict__ out,
                                int n_tok, int V) {
    __shared__ float s_w[HCHUNK][TOK_PER_BLK + 1];  // pad -> conflict-free both phases
    __shared__ int s_t[TOK_PER_BLK];
    __shared__ int s_v[TOK_PER_BLK];

    const int tid  = threadIdx.x;
    const int lane = tid & 31;
    const int w    = tid >> 5;
    const int base = blockIdx.x * TOK_PER_BLK;

    if (tid < TOK_PER_BLK) {
        int j = base + tid;
        s_v[tid] = (j < n_tok) ? g_sorted_v[j] : 0;   // clamp: valid addr
        s_t[tid] = (j < n_tok) ? g_sorted_t[j] : -1;  // -1 -> skip store
    }
    __syncthreads();

    // Load phase: lane owns token 'lane' (sorted values -> few sectors/warp).
    const int my_v = s_v[lane];

    // Store phase: warp w owns tokens 4w..4w+3.
    int st_t[4];
    #pragma unroll
    for (int q = 0; q < 4; q++) st_t[q] = s_t[(w << 2) + q];

    for (int c = 0; c < NCHUNK; c++) {
        const int h_base = c * HCHUNK;

        // ---- load phase: 16 independent gathers per thread ----
        #pragma unroll
        for (int i = 0; i < 16; i++) {
            int h_local = (i << 3) + w;  // warp w covers h_local = w, w+8, ...
            float val = __ldg(W + (size_t)(h_base + h_local) * (size_t)V + my_v);
            s_w[h_local][lane] = val;    // stride-1 across lanes: conflict-free
        }

        // bias for this lane's 4 h positions in the chunk
        float bl[4];
        #pragma unroll
        for (int hs = 0; hs < 4; hs++)
            bl[hs] = __ldg(bias + h_base + (hs << 5) + lane);

        __syncthreads();

        // ---- store phase: coalesced 128B rows ----
        #pragma unroll
        for (int q = 0; q < 4; q++) {
            const int j = (w << 2) + q;
            const int t = st_t[q];
            if (t < 0) continue;
            float* dst = out + (size_t)t * H_DIM + h_base;
            #pragma unroll
            for (int hs = 0; hs < 4; hs++) {
                int h_local = (hs << 5) + lane;
                float r = s_w[h_local][j] + bl[hs];  // stride-33: conflict-free
                __stcs(dst + h_local, r);
            }
        }
        __syncthreads();
    }
}

// ---------------- launch ----------------

extern "C" void kernel_launch(void* const* d_in, const int* in_sizes, int n_in,
                              void* d_out, int out_size) {
    const int*   seq  = (const int*)d_in[0];
    const float* W    = (const float*)d_in[1];
    const float* bias = (const float*)d_in[2];
    float*       out  = (float*)d_out;

    const int n_tok = in_sizes[0];            // 32768
    const int H     = in_sizes[2];            // 1024
    const int V     = in_sizes[1] / H;        // 50257
    const int nbuckets = (V + 7) >> 3;        // 6283
    (void)out_size; (void)n_in;

    hist_kernel<<<(n_tok + 255) / 256, 256>>>(seq, n_tok);
    scan_kernel<<<1, SCAN_THREADS>>>(nbuckets);
    scatter_kernel<<<(n_tok + 255) / 256, 256>>>(seq, n_tok);

    const int blocks = (n_tok + TOK_PER_BLK - 1) / TOK_PER_BLK;
    onehot_gather_xpose_kernel<<<blocks, THREADS>>>(W, bias, out, n_tok, V);
}